// round 1
// baseline (speedup 1.0000x reference)
#include <cuda_runtime.h>

#define K 7
#define HH 1024
#define WW 1024
#define CHUNKS 8

// scratch: per-(bin, chunk) partial sums
__device__ float g_partial[K * K * CHUNKS];

__device__ __forceinline__ void bin_extents(const float* __restrict__ region,
                                            int bi, int bj,
                                            int& r0, int& r1, int& c0, int& c1) {
    // Mirror the reference float32 arithmetic.
    float ci = region[0], cj = region[1], h = region[2], w = region[3];
    float i0 = ci - h * 0.5f, i1 = ci + h * 0.5f;
    float j0 = cj - w * 0.5f, j1 = cj + w * 0.5f;
    float stepi = (i1 - i0) / (float)(K + 1);
    float stepj = (j1 - j0) / (float)(K + 1);
    float ic = i0 + (float)(bi + 1) * stepi;
    float jc = j0 + (float)(bj + 1) * stepj;
    float bh2 = h / (float)K * 0.5f;
    float bw2 = w / (float)K * 0.5f;
    r0 = (int)floorf((ic - bh2) * (float)HH);
    r1 = (int)ceilf ((ic + bh2) * (float)HH);
    c0 = (int)floorf((jc - bw2) * (float)WW);
    c1 = (int)ceilf ((jc + bw2) * (float)WW);
    // clamp to valid pixel range (matches mask semantics of reference)
    r0 = max(r0, 0); r1 = min(r1, HH);
    c0 = max(c0, 0); c1 = min(c1, WW);
}

// Kernel 1: grid (49, CHUNKS). Each block sums one row-chunk of one bin.
__global__ void psroi_partial_kernel(const float* __restrict__ x,
                                     const float* __restrict__ region) {
    const int bin   = blockIdx.x;          // 0..48
    const int chunk = blockIdx.y;          // 0..CHUNKS-1
    const int bi = bin / K, bj = bin % K;

    int r0, r1, c0, c1;
    bin_extents(region, bi, bj, r0, r1, c0, c1);

    const int nrows = r1 - r0;
    const int ncols = c1 - c0;
    const int rpc   = (nrows + CHUNKS - 1) / CHUNKS;   // rows per chunk
    const int cr0   = r0 + chunk * rpc;
    const int cr1   = min(r1, cr0 + rpc);
    const int crows = max(cr1 - cr0, 0);

    const float* __restrict__ chan = x + (size_t)bin * HH * WW;

    const int total = crows * ncols;
    float acc = 0.0f;
    // coalesced: consecutive threads -> consecutive cols
    for (int idx = threadIdx.x; idx < total; idx += blockDim.x) {
        int rr = idx / ncols;
        int cc = idx - rr * ncols;
        acc += __ldg(&chan[(size_t)(cr0 + rr) * WW + (c0 + cc)]);
    }

    // deterministic block tree-reduction
    __shared__ float s[128];
    s[threadIdx.x] = acc;
    __syncthreads();
    for (int o = 64; o > 0; o >>= 1) {
        if (threadIdx.x < o) s[threadIdx.x] += s[threadIdx.x + o];
        __syncthreads();
    }
    if (threadIdx.x == 0)
        g_partial[bin * CHUNKS + chunk] = s[0];
}

// Kernel 2: single block, combine 49 bins deterministically.
__global__ void psroi_finalize_kernel(const float* __restrict__ region,
                                      float* __restrict__ out) {
    __shared__ float s[64];
    const int t = threadIdx.x;
    float score = 0.0f;
    if (t < K * K) {
        int bi = t / K, bj = t % K;
        int r0, r1, c0, c1;
        bin_extents(region, bi, bj, r0, r1, c0, c1);
        float sum = 0.0f;
        #pragma unroll
        for (int c = 0; c < CHUNKS; c++)
            sum += g_partial[t * CHUNKS + c];
        float cnt = (float)((r1 - r0) * (c1 - c0));
        score = sum / cnt;
    }
    s[t] = score;
    __syncthreads();
    for (int o = 32; o > 0; o >>= 1) {
        if (t < o) s[t] += s[t + o];
        __syncthreads();
    }
    if (t == 0) out[0] = s[0] / (float)(K * K);
}

extern "C" void kernel_launch(void* const* d_in, const int* in_sizes, int n_in,
                              void* d_out, int out_size) {
    const float* x      = (const float*)d_in[0];
    const float* region = (const float*)d_in[1];
    float* out = (float*)d_out;

    dim3 grid(K * K, CHUNKS);
    psroi_partial_kernel<<<grid, 128>>>(x, region);
    psroi_finalize_kernel<<<1, 64>>>(region, out);
}